// round 4
// baseline (speedup 1.0000x reference)
#include <cuda_runtime.h>

// Depthwise 3D Gaussian blur (xi=2, K=13, pad=6) on (1,3,192,192,192) fp32.
// Exactly separable: three 1D 13-tap passes (W, H, D).

#define NN 192
#define RR 6
#define KK 13

constexpr long PLANE = (long)NN * NN;          // 36864
constexpr long VOL   = (long)NN * NN * NN;     // 7077888
constexpr long TOTAL = 3 * VOL;                // 21233664

// Scratch (allocation-free rule: __device__ globals). 2 x 85 MB.
__device__ __align__(16) float g_tmpA[TOTAL];
__device__ __align__(16) float g_tmpB[TOTAL];

__device__ __forceinline__ void gauss_weights(float g[KK]) {
    float s = 0.f;
#pragma unroll
    for (int j = 0; j < KK; j++) {
        float d = (float)(j - RR);
        float v = expf(-d * d * 0.125f);   // xi=2 -> 1/(2*xi^2) = 0.125
        g[j] = v;
        s += v;
    }
    float inv = 1.0f / s;
#pragma unroll
    for (int j = 0; j < KK; j++) g[j] *= inv;
}

// ---------------- Pass 1: conv along W (contiguous axis), smem row tile ----
// blockDim = (192, 4): 4 rows per CTA, one thread per output element.
__global__ void conv_w_kernel(const float* __restrict__ in, float* __restrict__ out) {
    __shared__ float s[4][NN + 2 * RR];
    float g[KK];
    gauss_weights(g);

    const int t = threadIdx.x;             // 0..191
    const int y = threadIdx.y;             // 0..3
    const long line = (long)blockIdx.x * 4 + y;   // < 3*192*192 (grid exact)
    const float* p = in + line * NN;

    s[y][t + RR] = p[t];
    if (t < RR) {
        s[y][t] = 0.f;
        s[y][t + NN + RR] = 0.f;
    }
    __syncthreads();

    float acc = 0.f;
#pragma unroll
    for (int j = 0; j < KK; j++) acc += g[j] * s[y][t + j];

    out[line * NN + t] = acc;
}

// ---------------- Passes 2/3: conv along a strided axis (H or D) ----------
// float4 across W (threadIdx.x = 0..47). Sliding 13-wide float4 window along
// the conv axis; axis split into 4 segments of 48 outputs for CTA parallelism.
// All strides/offsets are in float4 units.
__global__ void conv_axis_kernel(const float4* __restrict__ in, float4* __restrict__ out,
                                 int cnt_lo, long s_lo, long s_hi, long stride) {
    float g[KK];
    gauss_weights(g);

    const int o = blockIdx.y * blockDim.y + threadIdx.y;   // line-group id, < 576
    const long base = (long)(o / cnt_lo) * s_hi + (long)(o % cnt_lo) * s_lo;
    const float4* pin = in + base + threadIdx.x;
    float4* pout = out + base + threadIdx.x;

    const int p0 = blockIdx.x * 48;        // segment start along conv axis

    float4 win[KK];
    const float4 zero4 = make_float4(0.f, 0.f, 0.f, 0.f);

    // Prime window with inputs at positions p0-6 .. p0+5
#pragma unroll
    for (int j = 0; j < KK - 1; j++) {
        int q = p0 - RR + j;
        float4 v = zero4;
        if (q >= 0 && q < NN) v = pin[(long)q * stride];
        win[j] = v;
    }

#pragma unroll
    for (int i = 0; i < 48; i++) {
        const int p = p0 + i;
        const int q = p + RR;
        float4 v = zero4;
        if (q < NN) v = pin[(long)q * stride];
        win[KK - 1] = v;

        float4 acc = make_float4(0.f, 0.f, 0.f, 0.f);
#pragma unroll
        for (int j = 0; j < KK; j++) {
            acc.x += g[j] * win[j].x;
            acc.y += g[j] * win[j].y;
            acc.z += g[j] * win[j].z;
            acc.w += g[j] * win[j].w;
        }
        pout[(long)p * stride] = acc;

#pragma unroll
        for (int j = 0; j < KK - 1; j++) win[j] = win[j + 1];
    }
}

extern "C" void kernel_launch(void* const* d_in, const int* in_sizes, int n_in,
                              void* d_out, int out_size) {
    const float* x = (const float*)d_in[0];   // (1,3,192,192,192) fp32
    float* out = (float*)d_out;

    void* pA = nullptr;
    void* pB = nullptr;
    cudaGetSymbolAddress(&pA, g_tmpA);
    cudaGetSymbolAddress(&pB, g_tmpB);
    float* tA = (float*)pA;
    float* tB = (float*)pB;

    // Pass 1: W axis. lines = 3*192*192 = 110592, 4 per CTA.
    conv_w_kernel<<<110592 / 4, dim3(192, 4)>>>(x, tA);

    // Pass 2: H axis. outer o = c*192 + d (576 lines-groups).
    // base = o * PLANE; stride along h = 192 floats = 48 float4.
    conv_axis_kernel<<<dim3(4, 576 / 4), dim3(48, 4)>>>(
        (const float4*)tA, (float4*)tB,
        /*cnt_lo=*/192, /*s_lo=*/PLANE / 4, /*s_hi=*/VOL / 4, /*stride=*/NN / 4);

    // Pass 3: D axis. outer o = c*192 + h.
    // base = c*VOL + h*192; stride along d = PLANE floats = 9216 float4.
    conv_axis_kernel<<<dim3(4, 576 / 4), dim3(48, 4)>>>(
        (const float4*)tB, (float4*)out,
        /*cnt_lo=*/192, /*s_lo=*/NN / 4, /*s_hi=*/VOL / 4, /*stride=*/PLANE / 4);
}

// round 5
// speedup vs baseline: 1.6054x; 1.6054x over previous
#include <cuda_runtime.h>
#include <math.h>

// Depthwise 3D Gaussian blur (xi=2, K=13, pad=6) on (1,3,192,192,192) fp32.
// Exactly separable: three 1D 13-tap passes (W, H, D).
// R4: weights precomputed on host (no per-thread expf), pass-1 vectorized x4,
//     packed f32x2 FMA in strided passes.

#define NN 192
#define RR 6
#define KK 13

constexpr long PLANE = (long)NN * NN;          // 36864
constexpr long VOL   = (long)NN * NN * NN;     // 7077888
constexpr long TOTAL = 3 * VOL;                // 21233664

// Scratch (allocation-free rule: __device__ globals). 2 x 85 MB.
__device__ __align__(16) float g_tmpA[TOTAL];
__device__ __align__(16) float g_tmpB[TOTAL];

struct GW { float g[KK]; };

// Packed fp32x2 FMA (Blackwell f32x2 pipe: 2 lanes per issue slot).
__device__ __forceinline__ float2 ffma2(float2 a, float2 b, float2 c) {
    float2 r;
    asm("fma.rn.f32x2 %0, %1, %2, %3;"
        : "=l"(reinterpret_cast<unsigned long long&>(r))
        : "l"(reinterpret_cast<unsigned long long&>(a)),
          "l"(reinterpret_cast<unsigned long long&>(b)),
          "l"(reinterpret_cast<unsigned long long&>(c)));
    return r;
}

// ---------------- Pass 1: conv along W (contiguous axis) -------------------
// 192 threads/CTA = 4 rows x 48 float4. Each thread: 1 LDG.128, 4 LDS.128
// (16B-stride = full crossbar throughput), 52 FMA, 1 STG.128 -> 4 outputs.
__global__ void conv_w_kernel(const float* __restrict__ in, float* __restrict__ out, GW gw) {
    __shared__ float s[4 * 204];   // per row: [0..5]=0, [6..197]=data, [198..203]=0

    const int tid = threadIdx.x;       // 0..191
    const int row = tid / 48;
    const int t   = tid % 48;
    const long line = (long)blockIdx.x * 4 + row;   // exact: grid = 110592/4

    float* sr = s + row * 204;
    const float4 v = ((const float4*)(in + line * NN))[t];

    // data at float offset 6+4t: 8B-aligned -> two float2 stores
    *(float2*)(sr + 6 + 4 * t)     = make_float2(v.x, v.y);
    *(float2*)(sr + 6 + 4 * t + 2) = make_float2(v.z, v.w);
    if (t < RR) { sr[t] = 0.f; sr[198 + t] = 0.f; }
    __syncthreads();

    // window x[c-6+j] = sr[c+j], c = 4t+k  ->  sr[4t .. 4t+15], 16B aligned
    float r[16];
    const float4* s4 = (const float4*)sr + t;
    float4 a0 = s4[0], a1 = s4[1], a2 = s4[2], a3 = s4[3];
    r[0]=a0.x; r[1]=a0.y; r[2]=a0.z; r[3]=a0.w;
    r[4]=a1.x; r[5]=a1.y; r[6]=a1.z; r[7]=a1.w;
    r[8]=a2.x; r[9]=a2.y; r[10]=a2.z; r[11]=a2.w;
    r[12]=a3.x; r[13]=a3.y; r[14]=a3.z; r[15]=a3.w;

    float o0 = 0.f, o1 = 0.f, o2 = 0.f, o3 = 0.f;
#pragma unroll
    for (int j = 0; j < KK; j++) {
        const float gj = gw.g[j];
        o0 = fmaf(gj, r[j],     o0);
        o1 = fmaf(gj, r[j + 1], o1);
        o2 = fmaf(gj, r[j + 2], o2);
        o3 = fmaf(gj, r[j + 3], o3);
    }
    ((float4*)(out + line * NN))[t] = make_float4(o0, o1, o2, o3);
}

// ---------------- Passes 2/3: conv along a strided axis (H or D) ----------
// float4 across W (threadIdx.x = 0..47). Sliding 13-wide window along the
// conv axis held as float2 pairs; packed FFMA2. Axis split into 4 segments
// of 48 outputs. All strides/offsets in float4 units.
__global__ void conv_axis_kernel(const float4* __restrict__ in, float4* __restrict__ out,
                                 GW gw, int cnt_lo, long s_lo, long s_hi, long stride) {
    const int o = blockIdx.y * blockDim.y + threadIdx.y;   // line-group id, < 576
    const long base = (long)(o / cnt_lo) * s_hi + (long)(o % cnt_lo) * s_lo;
    const float4* pin = in + base + threadIdx.x;
    float4* pout = out + base + threadIdx.x;

    const int p0 = blockIdx.x * 48;        // segment start along conv axis

    float2 w0[KK], w1[KK];                 // window: .xy / .zw halves
    const float2 z2 = make_float2(0.f, 0.f);

    // Prime window with inputs at positions p0-6 .. p0+5
#pragma unroll
    for (int j = 0; j < KK - 1; j++) {
        int q = p0 - RR + j;
        float2 a = z2, b = z2;
        if (q >= 0 && q < NN) {
            float4 v = pin[(long)q * stride];
            a = make_float2(v.x, v.y);
            b = make_float2(v.z, v.w);
        }
        w0[j] = a; w1[j] = b;
    }

#pragma unroll
    for (int i = 0; i < 48; i++) {
        const int p = p0 + i;
        const int q = p + RR;
        float2 a = z2, b = z2;
        if (q < NN) {
            float4 v = pin[(long)q * stride];
            a = make_float2(v.x, v.y);
            b = make_float2(v.z, v.w);
        }
        w0[KK - 1] = a; w1[KK - 1] = b;

        float2 acc0 = z2, acc1 = z2;
#pragma unroll
        for (int j = 0; j < KK; j++) {
            const float2 gj = make_float2(gw.g[j], gw.g[j]);
            acc0 = ffma2(gj, w0[j], acc0);
            acc1 = ffma2(gj, w1[j], acc1);
        }
        pout[(long)p * stride] = make_float4(acc0.x, acc0.y, acc1.x, acc1.y);

#pragma unroll
        for (int j = 0; j < KK - 1; j++) { w0[j] = w0[j + 1]; w1[j] = w1[j + 1]; }
    }
}

extern "C" void kernel_launch(void* const* d_in, const int* in_sizes, int n_in,
                              void* d_out, int out_size) {
    const float* x = (const float*)d_in[0];   // (1,3,192,192,192) fp32
    float* out = (float*)d_out;

    void* pA = nullptr;
    void* pB = nullptr;
    cudaGetSymbolAddress(&pA, g_tmpA);
    cudaGetSymbolAddress(&pB, g_tmpB);
    float* tA = (float*)pA;
    float* tB = (float*)pB;

    // Host-side weight computation (double precision, normalized Gaussian).
    GW gw;
    {
        double v[KK], s = 0.0;
        for (int j = 0; j < KK; j++) {
            double d = (double)(j - RR);
            v[j] = exp(-d * d / 8.0);      // xi = 2
            s += v[j];
        }
        for (int j = 0; j < KK; j++) gw.g[j] = (float)(v[j] / s);
    }

    // Pass 1: W axis. lines = 3*192*192 = 110592, 4 per CTA.
    conv_w_kernel<<<110592 / 4, 192>>>(x, tA, gw);

    // Pass 2: H axis. outer o = c*192 + d; stride along h = 48 float4.
    conv_axis_kernel<<<dim3(4, 576 / 4), dim3(48, 4)>>>(
        (const float4*)tA, (float4*)tB, gw,
        /*cnt_lo=*/192, /*s_lo=*/PLANE / 4, /*s_hi=*/VOL / 4, /*stride=*/NN / 4);

    // Pass 3: D axis. outer o = c*192 + h; stride along d = 9216 float4.
    conv_axis_kernel<<<dim3(4, 576 / 4), dim3(48, 4)>>>(
        (const float4*)tB, (float4*)out, gw,
        /*cnt_lo=*/192, /*s_lo=*/NN / 4, /*s_hi=*/VOL / 4, /*stride=*/PLANE / 4);
}

// round 7
// speedup vs baseline: 1.8950x; 1.1804x over previous
#include <cuda_runtime.h>
#include <math.h>

// Depthwise 3D Gaussian blur (xi=2, K=13, pad=6) on (1,3,192,192,192) fp32.
// R6 (= R5 resubmit after infra failure): fused W+H blur kernel (smem raw
// tile + register-sliding H window), then the D pass. 2 kernels, ~340 MB HBM.

#define NN 192
#define RR 6
#define KK 13

#define WT 48            // w-tile width in floats (12 float4)
#define ROWS 204         // h rows incl +-6 halo
#define RSTR 60          // floats per smem row (48 + 12 halo)
#define HSEG 24          // h outputs per thread

constexpr int PLANE = NN * NN;          // 36864
constexpr int VOL   = NN * NN * NN;     // 7077888
constexpr long TOTAL = 3L * VOL;

// Scratch (allocation-free rule): one 85 MB temp.
__device__ __align__(16) float g_tmpA[TOTAL];

struct GW { float g[KK]; };

// Packed fp32x2 FMA (Blackwell f32x2 pipe).
__device__ __forceinline__ float2 ffma2(float2 a, float2 b, float2 c) {
    float2 r;
    asm("fma.rn.f32x2 %0, %1, %2, %3;"
        : "=l"(reinterpret_cast<unsigned long long&>(r))
        : "l"(reinterpret_cast<unsigned long long&>(a)),
          "l"(reinterpret_cast<unsigned long long&>(b)),
          "l"(reinterpret_cast<unsigned long long&>(c)));
    return r;
}

// ---------------- Kernel 1: fused W + H blur on one (c,d) plane tile -------
// grid = (4 wchunks, 192 d, 3 c), block = 96 threads (12 float4-w x 8 h-groups).
__global__ __launch_bounds__(96) void conv_wh_kernel(const float* __restrict__ in,
                                                     float* __restrict__ out, GW gw) {
    __shared__ __align__(16) float s[ROWS * RSTR];   // 48,960 B

    const int c  = blockIdx.z;
    const int d  = blockIdx.y;
    const int w0 = blockIdx.x * WT;
    const int tid = threadIdx.x;

    const float* src = in + (c * NN + d) * PLANE;

    // ---- load raw tile: rows h-6..h+197, cols w0-6..w0+53, zeros outside --
    // 30 float2 per row; thread owns fixed (k, row-phase): tid = 3 row-phases
    // x 30 cols -> h strides by 3 covering 204 rows, no div/mod in loop.
    {
        const int k  = tid % 30;           // float2 column 0..29
        const int h0 = tid / 30;           // 0..3 (threads 90..95: h0=3, still <204 start ok)
        const int gwp = w0 - RR + 2 * k;
        const bool wok = (unsigned)gwp < NN;
        const float* colp = src + gwp;
        float* sp = s + 2 * k;
#pragma unroll 4
        for (int h = h0; h < ROWS; h += (96 / 30) + ((96 % 30) ? 0 : 0)) { /* placeholder */ }
        // (explicit loop below; stride = ceil distribution via 4 phases of 96/30)
        for (int h = h0; h < ROWS; h += 3) {
            if (tid >= 90 && h == h0 && h0 == 3) { /* threads 90..95 duplicate phase 3: harmless overwrite of same value */ }
            const int gh = h - RR;
            float2 v = make_float2(0.f, 0.f);
            if (wok && (unsigned)gh < NN)
                v = *(const float2*)(colp + gh * NN);
            *(float2*)(sp + h * RSTR) = v;
        }
    }
    __syncthreads();

    const int tw = tid % 12;     // float4 slot within w-tile
    const int hg = tid / 12;     // 0..7
    const int hbase = hg * HSEG; // local row base (== global h base of segment)

    float* dst = out + (c * NN + d) * PLANE + w0 + 4 * tw;

    // W-blur of local row r, float4 slot tw -> (lo: x,y) (hi: z,w)
    auto wblur = [&](int r, float2& lo, float2& hi) {
        const float* rp = s + r * RSTR + 4 * tw;
        const float4 x0 = *(const float4*)(rp);
        const float4 x1 = *(const float4*)(rp + 4);
        const float4 x2 = *(const float4*)(rp + 8);
        const float4 x3 = *(const float4*)(rp + 12);
        float rr[16] = {x0.x, x0.y, x0.z, x0.w, x1.x, x1.y, x1.z, x1.w,
                        x2.x, x2.y, x2.z, x2.w, x3.x, x3.y, x3.z, x3.w};
        float o0 = 0.f, o1 = 0.f, o2 = 0.f, o3 = 0.f;
#pragma unroll
        for (int j = 0; j < KK; j++) {
            const float gj = gw.g[j];
            o0 = fmaf(gj, rr[j],     o0);
            o1 = fmaf(gj, rr[j + 1], o1);
            o2 = fmaf(gj, rr[j + 2], o2);
            o3 = fmaf(gj, rr[j + 3], o3);
        }
        lo = make_float2(o0, o1);
        hi = make_float2(o2, o3);
    };

    // 13-deep sliding window of W-blurred float4 rows
    float2 a[KK], b[KK];
#pragma unroll
    for (int j = 0; j < KK - 1; j++) wblur(hbase + j, a[j], b[j]);

#pragma unroll
    for (int i = 0; i < HSEG; i++) {
        wblur(hbase + i + (KK - 1), a[KK - 1], b[KK - 1]);

        float2 acc0 = make_float2(0.f, 0.f);
        float2 acc1 = make_float2(0.f, 0.f);
#pragma unroll
        for (int j = 0; j < KK; j++) {
            const float2 gj = make_float2(gw.g[j], gw.g[j]);
            acc0 = ffma2(gj, a[j], acc0);
            acc1 = ffma2(gj, b[j], acc1);
        }
        *(float4*)(dst + (hbase + i) * NN) = make_float4(acc0.x, acc0.y, acc1.x, acc1.y);

#pragma unroll
        for (int j = 0; j < KK - 1; j++) { a[j] = a[j + 1]; b[j] = b[j + 1]; }
    }
}

// ---------------- Kernel 2: conv along D (strided axis) --------------------
// float4 across W (threadIdx.x = 0..47), sliding 13-wide register window
// along d; axis split into 4 segments of 48. Strides in float4 units.
__global__ void conv_axis_kernel(const float4* __restrict__ in, float4* __restrict__ out,
                                 GW gw, int cnt_lo, int s_lo, int s_hi, int stride) {
    const int o = blockIdx.y * blockDim.y + threadIdx.y;   // c*192 + h, < 576
    const int base = (o / cnt_lo) * s_hi + (o % cnt_lo) * s_lo;
    const float4* pin = in + base + threadIdx.x;
    float4* pout = out + base + threadIdx.x;

    const int p0 = blockIdx.x * 48;

    float2 w0[KK], w1[KK];
    const float2 z2 = make_float2(0.f, 0.f);

#pragma unroll
    for (int j = 0; j < KK - 1; j++) {
        int q = p0 - RR + j;
        float2 aa = z2, bb = z2;
        if (q >= 0 && q < NN) {
            float4 v = pin[q * stride];
            aa = make_float2(v.x, v.y);
            bb = make_float2(v.z, v.w);
        }
        w0[j] = aa; w1[j] = bb;
    }

#pragma unroll
    for (int i = 0; i < 48; i++) {
        const int p = p0 + i;
        const int q = p + RR;
        float2 aa = z2, bb = z2;
        if (q < NN) {
            float4 v = pin[q * stride];
            aa = make_float2(v.x, v.y);
            bb = make_float2(v.z, v.w);
        }
        w0[KK - 1] = aa; w1[KK - 1] = bb;

        float2 acc0 = z2, acc1 = z2;
#pragma unroll
        for (int j = 0; j < KK; j++) {
            const float2 gj = make_float2(gw.g[j], gw.g[j]);
            acc0 = ffma2(gj, w0[j], acc0);
            acc1 = ffma2(gj, w1[j], acc1);
        }
        pout[p * stride] = make_float4(acc0.x, acc0.y, acc1.x, acc1.y);

#pragma unroll
        for (int j = 0; j < KK - 1; j++) { w0[j] = w0[j + 1]; w1[j] = w1[j + 1]; }
    }
}

extern "C" void kernel_launch(void* const* d_in, const int* in_sizes, int n_in,
                              void* d_out, int out_size) {
    const float* x = (const float*)d_in[0];   // (1,3,192,192,192) fp32
    float* out = (float*)d_out;

    void* pA = nullptr;
    cudaGetSymbolAddress(&pA, g_tmpA);
    float* tA = (float*)pA;

    // Host-side weights (double precision, normalized Gaussian, xi=2).
    GW gw;
    {
        double v[KK], s = 0.0;
        for (int j = 0; j < KK; j++) {
            double dd = (double)(j - RR);
            v[j] = exp(-dd * dd / 8.0);
            s += v[j];
        }
        for (int j = 0; j < KK; j++) gw.g[j] = (float)(v[j] / s);
    }

    // Fused W+H blur: x -> tA
    conv_wh_kernel<<<dim3(NN / WT, NN, 3), 96>>>(x, tA, gw);

    // D pass: tA -> out. outer o = c*192 + h; stride along d = 9216 float4.
    conv_axis_kernel<<<dim3(4, 576 / 4), dim3(48, 4)>>>(
        (const float4*)tA, (float4*)out, gw,
        /*cnt_lo=*/NN, /*s_lo=*/NN / 4, /*s_hi=*/VOL / 4, /*stride=*/PLANE / 4);
}